// round 2
// baseline (speedup 1.0000x reference)
#include <cuda_runtime.h>
#include <math.h>
#include <stdint.h>

#define N_NODES 100000
#define N_EDGES 1600000
#define IN_F 64
#define HID_F 64
#define OUT_F 16

// ---- scratch (static __device__ globals; no allocation allowed) ----
__device__ int   g_is64;                          // 1 if edge_index is int64
__device__ __align__(16) float g_dis[N_NODES];    // deg -> rsqrt(deg)
__device__ __align__(16) int   g_src[N_EDGES];
__device__ __align__(16) int   g_dst[N_EDGES];
__device__ __align__(16) float g_norm[N_EDGES];   // dis[src]*dis[dst]
__device__ __align__(16) float g_h1[(size_t)N_NODES * HID_F];
__device__ __align__(16) float g_agg1[(size_t)N_NODES * HID_F];
__device__ __align__(16) float g_h2[(size_t)N_NODES * OUT_F];
__device__ __align__(16) float g_agg2[(size_t)N_NODES * OUT_F];

// red.global.add.v4.f32 — no-return vectorized reduction (sm_90+)
__device__ __forceinline__ void red_add_v4(float* p, float4 v) {
    asm volatile("red.global.add.v4.f32 [%0], {%1, %2, %3, %4};"
                 :: "l"(p), "f"(v.x), "f"(v.y), "f"(v.z), "f"(v.w)
                 : "memory");
}

__device__ __forceinline__ void red_add_f32(float* p, float v) {
    asm volatile("red.global.add.f32 [%0], %1;" :: "l"(p), "f"(v) : "memory");
}

// ---------------------------------------------------------------------------
// 0) detect edge_index dtype: int64 values < 2^31 have zero odd 32-bit words
__global__ void detect_kernel(const int* __restrict__ ei32, int E) {
    if (blockIdx.x != 0 || threadIdx.x != 0) return;
    int is64 = 1;
    int n = E < 16 ? E : 16;
    for (int i = 0; i < n; i++)
        if (ei32[2 * i + 1] != 0) is64 = 0;
    g_is64 = is64;
}

// 1) deg init (self-loop contributes 1)
__global__ void init_deg_kernel(int N) {
    int i = blockIdx.x * blockDim.x + threadIdx.x;
    if (i < N) g_dis[i] = 1.0f;
}

// 2) materialize src/dst as int32 + count degree on dst
__global__ void build_edges_kernel(const int* __restrict__ ei32, int E) {
    int e = blockIdx.x * blockDim.x + threadIdx.x;
    if (e >= E) return;
    int stride = g_is64 ? 2 : 1;
    int src = ei32[(size_t)e * stride];
    int dst = ei32[((size_t)E + e) * stride];
    g_src[e] = src;
    g_dst[e] = dst;
    red_add_f32(&g_dis[dst], 1.0f);
}

// 3) deg -> dis = rsqrt(deg)
__global__ void rsqrt_kernel(int N) {
    int i = blockIdx.x * blockDim.x + threadIdx.x;
    if (i < N) g_dis[i] = rsqrtf(g_dis[i]);
}

// 4) per-edge norm
__global__ void norm_kernel(int E) {
    int e = blockIdx.x * blockDim.x + threadIdx.x;
    if (e >= E) return;
    g_norm[e] = g_dis[g_src[e]] * g_dis[g_dst[e]];
}

// ---------------------------------------------------------------------------
// 5) GEMM1: h1 = x @ W1; also init agg1 with self-loop term h1 * dis^2
__global__ void gemm1_kernel(const float* __restrict__ x,
                             const float* __restrict__ W1, int N) {
    __shared__ float Wsh[IN_F * HID_F];
    for (int i = threadIdx.x; i < IN_F * HID_F; i += blockDim.x)
        Wsh[i] = W1[i];
    __syncthreads();

    int n = blockIdx.x * blockDim.x + threadIdx.x;
    if (n >= N) return;

    float acc[HID_F];
#pragma unroll
    for (int j = 0; j < HID_F; j++) acc[j] = 0.0f;

    const float4* xrow = reinterpret_cast<const float4*>(x + (size_t)n * IN_F);
#pragma unroll 1
    for (int k4 = 0; k4 < IN_F / 4; k4++) {
        float4 xv = __ldg(xrow + k4);
        float xk[4] = {xv.x, xv.y, xv.z, xv.w};
#pragma unroll
        for (int kk = 0; kk < 4; kk++) {
            const float4* wrow =
                reinterpret_cast<const float4*>(&Wsh[(k4 * 4 + kk) * HID_F]);
#pragma unroll
            for (int j4 = 0; j4 < HID_F / 4; j4++) {
                float4 w = wrow[j4];
                acc[j4 * 4 + 0] += xk[kk] * w.x;
                acc[j4 * 4 + 1] += xk[kk] * w.y;
                acc[j4 * 4 + 2] += xk[kk] * w.z;
                acc[j4 * 4 + 3] += xk[kk] * w.w;
            }
        }
    }

    float dis = g_dis[n];
    float sl = dis * dis;
    float4* h1row = reinterpret_cast<float4*>(&g_h1[(size_t)n * HID_F]);
    float4* a1row = reinterpret_cast<float4*>(&g_agg1[(size_t)n * HID_F]);
#pragma unroll
    for (int j4 = 0; j4 < HID_F / 4; j4++) {
        float4 v = make_float4(acc[j4 * 4 + 0], acc[j4 * 4 + 1],
                               acc[j4 * 4 + 2], acc[j4 * 4 + 3]);
        h1row[j4] = v;
        a1row[j4] = make_float4(v.x * sl, v.y * sl, v.z * sl, v.w * sl);
    }
}

// 6) scatter layer 1: agg1[dst] += h1[src] * norm[e], 16 float4 chunks/edge
__global__ void scatter1_kernel(int E) {
    long long tid = (long long)blockIdx.x * blockDim.x + threadIdx.x;
    int e = (int)(tid >> 4);
    int c = (int)(tid & 15);
    if (e >= E) return;
    int src = g_src[e];
    int dst = g_dst[e];
    float nrm = g_norm[e];
    float4 v = *reinterpret_cast<const float4*>(&g_h1[(size_t)src * HID_F + c * 4]);
    v.x *= nrm; v.y *= nrm; v.z *= nrm; v.w *= nrm;
    red_add_v4(&g_agg1[(size_t)dst * HID_F + c * 4], v);
}

// 7) GEMM2: h2 = relu(agg1 + b1) @ W2; init agg2 with self-loop term
__global__ void gemm2_kernel(const float* __restrict__ W2,
                             const float* __restrict__ b1, int N) {
    __shared__ float Wsh[HID_F * OUT_F];
    __shared__ float bsh[HID_F];
    for (int i = threadIdx.x; i < HID_F * OUT_F; i += blockDim.x)
        Wsh[i] = W2[i];
    if (threadIdx.x < HID_F) bsh[threadIdx.x] = b1[threadIdx.x];
    __syncthreads();

    int n = blockIdx.x * blockDim.x + threadIdx.x;
    if (n >= N) return;

    float acc[OUT_F];
#pragma unroll
    for (int j = 0; j < OUT_F; j++) acc[j] = 0.0f;

    const float4* arow =
        reinterpret_cast<const float4*>(&g_agg1[(size_t)n * HID_F]);
#pragma unroll 1
    for (int k4 = 0; k4 < HID_F / 4; k4++) {
        float4 av = arow[k4];
        float a[4] = {av.x, av.y, av.z, av.w};
#pragma unroll
        for (int kk = 0; kk < 4; kk++) {
            int k = k4 * 4 + kk;
            float h = fmaxf(a[kk] + bsh[k], 0.0f);
            const float4* wrow =
                reinterpret_cast<const float4*>(&Wsh[k * OUT_F]);
#pragma unroll
            for (int j4 = 0; j4 < OUT_F / 4; j4++) {
                float4 w = wrow[j4];
                acc[j4 * 4 + 0] += h * w.x;
                acc[j4 * 4 + 1] += h * w.y;
                acc[j4 * 4 + 2] += h * w.z;
                acc[j4 * 4 + 3] += h * w.w;
            }
        }
    }

    float dis = g_dis[n];
    float sl = dis * dis;
    float4* h2row = reinterpret_cast<float4*>(&g_h2[(size_t)n * OUT_F]);
    float4* a2row = reinterpret_cast<float4*>(&g_agg2[(size_t)n * OUT_F]);
#pragma unroll
    for (int j4 = 0; j4 < OUT_F / 4; j4++) {
        float4 v = make_float4(acc[j4 * 4 + 0], acc[j4 * 4 + 1],
                               acc[j4 * 4 + 2], acc[j4 * 4 + 3]);
        h2row[j4] = v;
        a2row[j4] = make_float4(v.x * sl, v.y * sl, v.z * sl, v.w * sl);
    }
}

// 8) scatter layer 2: agg2[dst] += h2[src] * norm[e], 4 float4 chunks/edge
__global__ void scatter2_kernel(int E) {
    long long tid = (long long)blockIdx.x * blockDim.x + threadIdx.x;
    int e = (int)(tid >> 2);
    int c = (int)(tid & 3);
    if (e >= E) return;
    int src = g_src[e];
    int dst = g_dst[e];
    float nrm = g_norm[e];
    float4 v = *reinterpret_cast<const float4*>(&g_h2[(size_t)src * OUT_F + c * 4]);
    v.x *= nrm; v.y *= nrm; v.z *= nrm; v.w *= nrm;
    red_add_v4(&g_agg2[(size_t)dst * OUT_F + c * 4], v);
}

// 9) out = log_softmax(agg2 + b2) per row
__global__ void lsm_kernel(const float* __restrict__ b2,
                           float* __restrict__ out, int N) {
    int n = blockIdx.x * blockDim.x + threadIdx.x;
    if (n >= N) return;
    float v[OUT_F];
    const float4* arow =
        reinterpret_cast<const float4*>(&g_agg2[(size_t)n * OUT_F]);
#pragma unroll
    for (int j4 = 0; j4 < OUT_F / 4; j4++) {
        float4 a = arow[j4];
        v[j4 * 4 + 0] = a.x + b2[j4 * 4 + 0];
        v[j4 * 4 + 1] = a.y + b2[j4 * 4 + 1];
        v[j4 * 4 + 2] = a.z + b2[j4 * 4 + 2];
        v[j4 * 4 + 3] = a.w + b2[j4 * 4 + 3];
    }
    float mx = v[0];
#pragma unroll
    for (int j = 1; j < OUT_F; j++) mx = fmaxf(mx, v[j]);
    float s = 0.0f;
#pragma unroll
    for (int j = 0; j < OUT_F; j++) s += __expf(v[j] - mx);
    float ls = mx + logf(s);
    float4* orow = reinterpret_cast<float4*>(out + (size_t)n * OUT_F);
#pragma unroll
    for (int j4 = 0; j4 < OUT_F / 4; j4++)
        orow[j4] = make_float4(v[j4 * 4 + 0] - ls, v[j4 * 4 + 1] - ls,
                               v[j4 * 4 + 2] - ls, v[j4 * 4 + 3] - ls);
}

// ---------------------------------------------------------------------------
extern "C" void kernel_launch(void* const* d_in, const int* in_sizes, int n_in,
                              void* d_out, int out_size) {
    const float* x    = (const float*)d_in[0];
    const int*   ei32 = (const int*)d_in[1];   // int32 OR int64 (detected on device)
    const float* W1   = (const float*)d_in[2];
    const float* b1   = (const float*)d_in[3];
    const float* W2   = (const float*)d_in[4];
    const float* b2   = (const float*)d_in[5];
    float* out = (float*)d_out;

    int N = in_sizes[0] / IN_F;
    int E = in_sizes[1] / 2;

    const int T = 256;
    int gN = (N + T - 1) / T;
    int gE = (E + T - 1) / T;

    detect_kernel<<<1, 32>>>(ei32, E);
    init_deg_kernel<<<gN, T>>>(N);
    build_edges_kernel<<<gE, T>>>(ei32, E);
    rsqrt_kernel<<<gN, T>>>(N);
    norm_kernel<<<gE, T>>>(E);

    gemm1_kernel<<<gN, T>>>(x, W1, N);

    long long w1 = (long long)E * 16;
    scatter1_kernel<<<(unsigned)((w1 + T - 1) / T), T>>>(E);

    gemm2_kernel<<<gN, T>>>(W2, b1, N);

    long long w2 = (long long)E * 4;
    scatter2_kernel<<<(unsigned)((w2 + T - 1) / T), T>>>(E);

    lsm_kernel<<<gN, T>>>(b2, out, N);
}

// round 3
// speedup vs baseline: 1.3768x; 1.3768x over previous
#include <cuda_runtime.h>
#include <math.h>
#include <stdint.h>

#define N_NODES 100000
#define N_EDGES 1600000
#define IN_F 64
#define HID_F 64
#define OUT_F 16

#define SCAN_B 1024
#define N_SCAN_BLKS ((N_NODES + SCAN_B - 1) / SCAN_B)   // 98

// ---- scratch (static __device__ globals; no allocation allowed) ----
__device__ int   g_is64;
__device__ __align__(16) int   g_cnt[N_NODES];      // in-degree (no self-loop)
__device__ __align__(16) int   g_row[N_NODES];      // CSR exclusive offsets
__device__ __align__(16) int   g_cur[N_NODES];      // fill cursors
__device__ __align__(16) int   g_blksum[128];
__device__ __align__(16) float g_dis[N_NODES];      // rsqrt(deg+1)
__device__ __align__(16) int   g_srcl[N_EDGES];
__device__ __align__(16) int   g_dstl[N_EDGES];
__device__ __align__(16) int   g_csr_src[N_EDGES];
__device__ __align__(16) float g_h1[(size_t)N_NODES * HID_F];   // (x@W1)*dis
__device__ __align__(16) float g_agg1[(size_t)N_NODES * HID_F];
__device__ __align__(16) float g_h2[(size_t)N_NODES * OUT_F];   // (relu(..)@W2)*dis
__device__ __align__(16) float g_agg2[(size_t)N_NODES * OUT_F];

// ---------------------------------------------------------------------------
// 0) detect edge_index dtype (int64 values < 2^31 -> odd 32-bit words zero)
__global__ void detect_kernel(const int* __restrict__ ei32, int E) {
    if (blockIdx.x != 0 || threadIdx.x != 0) return;
    int is64 = 1;
    int n = E < 16 ? E : 16;
    for (int i = 0; i < n; i++)
        if (ei32[2 * i + 1] != 0) is64 = 0;
    g_is64 = is64;
}

// 1) zero degree counters
__global__ void zero_cnt_kernel(int N) {
    int i = blockIdx.x * blockDim.x + threadIdx.x;
    if (i < N) g_cnt[i] = 0;
}

// 2) extract src/dst as int32 + degree histogram on dst
__global__ void build_edges_kernel(const int* __restrict__ ei32, int E) {
    int e = blockIdx.x * blockDim.x + threadIdx.x;
    if (e >= E) return;
    int stride = g_is64 ? 2 : 1;
    int src = ei32[(size_t)e * stride];
    int dst = ei32[((size_t)E + e) * stride];
    g_srcl[e] = src;
    g_dstl[e] = dst;
    atomicAdd(&g_cnt[dst], 1);
}

// 3a) per-block exclusive scan of g_cnt -> g_row, block totals -> g_blksum
__global__ void scan1_kernel(int N) {
    __shared__ int sh[SCAN_B];
    int i = blockIdx.x * SCAN_B + threadIdx.x;
    int v = (i < N) ? g_cnt[i] : 0;
    sh[threadIdx.x] = v;
    __syncthreads();
#pragma unroll
    for (int off = 1; off < SCAN_B; off *= 2) {
        int t = (threadIdx.x >= off) ? sh[threadIdx.x - off] : 0;
        __syncthreads();
        sh[threadIdx.x] += t;
        __syncthreads();
    }
    if (i < N) g_row[i] = sh[threadIdx.x] - v;   // exclusive
    if (threadIdx.x == SCAN_B - 1) g_blksum[blockIdx.x] = sh[SCAN_B - 1];
}

// 3b) exclusive scan of block totals (single block)
__global__ void scan2_kernel(int nb) {
    __shared__ int sh[128];
    int v = (threadIdx.x < nb) ? g_blksum[threadIdx.x] : 0;
    sh[threadIdx.x] = v;
    __syncthreads();
#pragma unroll
    for (int off = 1; off < 128; off *= 2) {
        int t = (threadIdx.x >= off) ? sh[threadIdx.x - off] : 0;
        __syncthreads();
        sh[threadIdx.x] += t;
        __syncthreads();
    }
    if (threadIdx.x < nb) g_blksum[threadIdx.x] = sh[threadIdx.x] - v;
}

// 3c) fixup offsets, init cursors, compute dis = rsqrt(deg+1)
__global__ void scan3_kernel(int N) {
    int i = blockIdx.x * blockDim.x + threadIdx.x;
    if (i >= N) return;
    int r = g_row[i] + g_blksum[i >> 10];
    g_row[i] = r;
    g_cur[i] = r;
    g_dis[i] = rsqrtf((float)(g_cnt[i] + 1));
}

// 4) bucket fill: csr_src grouped by dst
__global__ void fill_kernel(int E) {
    int e = blockIdx.x * blockDim.x + threadIdx.x;
    if (e >= E) return;
    int dst = g_dstl[e];
    int pos = atomicAdd(&g_cur[dst], 1);
    g_csr_src[pos] = g_srcl[e];
}

// ---------------------------------------------------------------------------
// 5) GEMM1: h1s = (x @ W1) * dis[n]
__global__ void gemm1_kernel(const float* __restrict__ x,
                             const float* __restrict__ W1, int N) {
    __shared__ float Wsh[IN_F * HID_F];
    for (int i = threadIdx.x; i < IN_F * HID_F; i += blockDim.x)
        Wsh[i] = W1[i];
    __syncthreads();

    int n = blockIdx.x * blockDim.x + threadIdx.x;
    if (n >= N) return;

    float acc[HID_F];
#pragma unroll
    for (int j = 0; j < HID_F; j++) acc[j] = 0.0f;

    const float4* xrow = reinterpret_cast<const float4*>(x + (size_t)n * IN_F);
#pragma unroll 1
    for (int k4 = 0; k4 < IN_F / 4; k4++) {
        float4 xv = __ldg(xrow + k4);
        float xk[4] = {xv.x, xv.y, xv.z, xv.w};
#pragma unroll
        for (int kk = 0; kk < 4; kk++) {
            const float4* wrow =
                reinterpret_cast<const float4*>(&Wsh[(k4 * 4 + kk) * HID_F]);
#pragma unroll
            for (int j4 = 0; j4 < HID_F / 4; j4++) {
                float4 w = wrow[j4];
                acc[j4 * 4 + 0] += xk[kk] * w.x;
                acc[j4 * 4 + 1] += xk[kk] * w.y;
                acc[j4 * 4 + 2] += xk[kk] * w.z;
                acc[j4 * 4 + 3] += xk[kk] * w.w;
            }
        }
    }

    float dis = g_dis[n];
    float4* h1row = reinterpret_cast<float4*>(&g_h1[(size_t)n * HID_F]);
#pragma unroll
    for (int j4 = 0; j4 < HID_F / 4; j4++)
        h1row[j4] = make_float4(acc[j4 * 4 + 0] * dis, acc[j4 * 4 + 1] * dis,
                                acc[j4 * 4 + 2] * dis, acc[j4 * 4 + 3] * dis);
}

// 6) gather layer 1: agg1[n] = dis[n] * (h1s[n] + sum_{src in in(n)} h1s[src])
//    16 threads per node, one float4 chunk each. Atomic-free.
__global__ void gather1_kernel(int N) {
    int t = blockIdx.x * blockDim.x + threadIdx.x;
    int n = t >> 4;
    int c = t & 15;
    if (n >= N) return;
    int beg = g_row[n];
    int end = beg + g_cnt[n];

    // self-loop term
    float4 acc = *reinterpret_cast<const float4*>(&g_h1[(size_t)n * HID_F + c * 4]);

    for (int j = beg; j < end; j++) {
        int s = __ldg(&g_csr_src[j]);
        float4 v = *reinterpret_cast<const float4*>(&g_h1[(size_t)s * HID_F + c * 4]);
        acc.x += v.x; acc.y += v.y; acc.z += v.z; acc.w += v.w;
    }
    float d = g_dis[n];
    *reinterpret_cast<float4*>(&g_agg1[(size_t)n * HID_F + c * 4]) =
        make_float4(acc.x * d, acc.y * d, acc.z * d, acc.w * d);
}

// 7) GEMM2: h2s = (relu(agg1 + b1) @ W2) * dis[n]
__global__ void gemm2_kernel(const float* __restrict__ W2,
                             const float* __restrict__ b1, int N) {
    __shared__ float Wsh[HID_F * OUT_F];
    __shared__ float bsh[HID_F];
    for (int i = threadIdx.x; i < HID_F * OUT_F; i += blockDim.x)
        Wsh[i] = W2[i];
    if (threadIdx.x < HID_F) bsh[threadIdx.x] = b1[threadIdx.x];
    __syncthreads();

    int n = blockIdx.x * blockDim.x + threadIdx.x;
    if (n >= N) return;

    float acc[OUT_F];
#pragma unroll
    for (int j = 0; j < OUT_F; j++) acc[j] = 0.0f;

    const float4* arow =
        reinterpret_cast<const float4*>(&g_agg1[(size_t)n * HID_F]);
#pragma unroll 1
    for (int k4 = 0; k4 < HID_F / 4; k4++) {
        float4 av = arow[k4];
        float a[4] = {av.x, av.y, av.z, av.w};
#pragma unroll
        for (int kk = 0; kk < 4; kk++) {
            int k = k4 * 4 + kk;
            float h = fmaxf(a[kk] + bsh[k], 0.0f);
            const float4* wrow =
                reinterpret_cast<const float4*>(&Wsh[k * OUT_F]);
#pragma unroll
            for (int j4 = 0; j4 < OUT_F / 4; j4++) {
                float4 w = wrow[j4];
                acc[j4 * 4 + 0] += h * w.x;
                acc[j4 * 4 + 1] += h * w.y;
                acc[j4 * 4 + 2] += h * w.z;
                acc[j4 * 4 + 3] += h * w.w;
            }
        }
    }

    float dis = g_dis[n];
    float4* h2row = reinterpret_cast<float4*>(&g_h2[(size_t)n * OUT_F]);
#pragma unroll
    for (int j4 = 0; j4 < OUT_F / 4; j4++)
        h2row[j4] = make_float4(acc[j4 * 4 + 0] * dis, acc[j4 * 4 + 1] * dis,
                                acc[j4 * 4 + 2] * dis, acc[j4 * 4 + 3] * dis);
}

// 8) gather layer 2: agg2[n] = dis[n] * (h2s[n] + sum h2s[src]); 4 threads/node
__global__ void gather2_kernel(int N) {
    int t = blockIdx.x * blockDim.x + threadIdx.x;
    int n = t >> 2;
    int c = t & 3;
    if (n >= N) return;
    int beg = g_row[n];
    int end = beg + g_cnt[n];

    float4 acc = *reinterpret_cast<const float4*>(&g_h2[(size_t)n * OUT_F + c * 4]);

    for (int j = beg; j < end; j++) {
        int s = __ldg(&g_csr_src[j]);
        float4 v = *reinterpret_cast<const float4*>(&g_h2[(size_t)s * OUT_F + c * 4]);
        acc.x += v.x; acc.y += v.y; acc.z += v.z; acc.w += v.w;
    }
    float d = g_dis[n];
    *reinterpret_cast<float4*>(&g_agg2[(size_t)n * OUT_F + c * 4]) =
        make_float4(acc.x * d, acc.y * d, acc.z * d, acc.w * d);
}

// 9) out = log_softmax(agg2 + b2)
__global__ void lsm_kernel(const float* __restrict__ b2,
                           float* __restrict__ out, int N) {
    int n = blockIdx.x * blockDim.x + threadIdx.x;
    if (n >= N) return;
    float v[OUT_F];
    const float4* arow =
        reinterpret_cast<const float4*>(&g_agg2[(size_t)n * OUT_F]);
#pragma unroll
    for (int j4 = 0; j4 < OUT_F / 4; j4++) {
        float4 a = arow[j4];
        v[j4 * 4 + 0] = a.x + b2[j4 * 4 + 0];
        v[j4 * 4 + 1] = a.y + b2[j4 * 4 + 1];
        v[j4 * 4 + 2] = a.z + b2[j4 * 4 + 2];
        v[j4 * 4 + 3] = a.w + b2[j4 * 4 + 3];
    }
    float mx = v[0];
#pragma unroll
    for (int j = 1; j < OUT_F; j++) mx = fmaxf(mx, v[j]);
    float s = 0.0f;
#pragma unroll
    for (int j = 0; j < OUT_F; j++) s += __expf(v[j] - mx);
    float ls = mx + logf(s);
    float4* orow = reinterpret_cast<float4*>(out + (size_t)n * OUT_F);
#pragma unroll
    for (int j4 = 0; j4 < OUT_F / 4; j4++)
        orow[j4] = make_float4(v[j4 * 4 + 0] - ls, v[j4 * 4 + 1] - ls,
                               v[j4 * 4 + 2] - ls, v[j4 * 4 + 3] - ls);
}

// ---------------------------------------------------------------------------
extern "C" void kernel_launch(void* const* d_in, const int* in_sizes, int n_in,
                              void* d_out, int out_size) {
    const float* x    = (const float*)d_in[0];
    const int*   ei32 = (const int*)d_in[1];
    const float* W1   = (const float*)d_in[2];
    const float* b1   = (const float*)d_in[3];
    const float* W2   = (const float*)d_in[4];
    const float* b2   = (const float*)d_in[5];
    float* out = (float*)d_out;

    int N = in_sizes[0] / IN_F;
    int E = in_sizes[1] / 2;

    const int T = 256;
    int gN = (N + T - 1) / T;
    int gE = (E + T - 1) / T;
    int nScanBlks = (N + SCAN_B - 1) / SCAN_B;

    detect_kernel<<<1, 32>>>(ei32, E);
    zero_cnt_kernel<<<gN, T>>>(N);
    build_edges_kernel<<<gE, T>>>(ei32, E);
    scan1_kernel<<<nScanBlks, SCAN_B>>>(N);
    scan2_kernel<<<1, 128>>>(nScanBlks);
    scan3_kernel<<<gN, T>>>(N);
    fill_kernel<<<gE, T>>>(E);

    gemm1_kernel<<<gN, T>>>(x, W1, N);
    gather1_kernel<<<(N * 16 + T - 1) / T, T>>>(N);
    gemm2_kernel<<<gN, T>>>(W2, b1, N);
    gather2_kernel<<<(N * 4 + T - 1) / T, T>>>(N);
    lsm_kernel<<<gN, T>>>(b2, out, N);
}

// round 5
// speedup vs baseline: 1.4388x; 1.0451x over previous
#include <cuda_runtime.h>
#include <cuda_fp16.h>
#include <math.h>
#include <stdint.h>

#define N_NODES 100000
#define N_EDGES 1600000
#define IN_F 64
#define HID_F 64
#define OUT_F 16

#define SCAN_B 1024
#define MAX_SCAN_BLKS 128

// ---- scratch (static __device__ globals; zero-initialized at module load) ----
__device__ __align__(16) int    g_cnt[N_NODES];     // in-degree (re-zeroed by last kernel)
__device__ __align__(16) int    g_row[N_NODES];     // CSR exclusive offsets
__device__ __align__(16) int    g_cur[N_NODES];     // fill cursors
__device__ __align__(16) int    g_blksum[MAX_SCAN_BLKS];
__device__ __align__(16) float  g_dis[N_NODES];     // rsqrt(deg+1)
__device__ __align__(16) int2   g_csr[N_EDGES];     // (src, bits(dis[src]))
__device__ __align__(16) __half g_h1[(size_t)N_NODES * HID_F];  // x@W1 (unscaled, fp16)
__device__ __align__(16) float  g_agg1[(size_t)N_NODES * HID_F];
__device__ __align__(16) float  g_h2[(size_t)N_NODES * OUT_F];  // relu(..)@W2 (unscaled)

// inline dtype detect: int64 node ids < 2^31 have zero odd 32-bit words
__device__ __forceinline__ int edge_stride(const int* __restrict__ ei32, int E) {
    int is64 = 1;
    int n = E < 16 ? E : 16;
#pragma unroll
    for (int i = 0; i < 16; i++)
        if (i < n && ei32[2 * i + 1] != 0) is64 = 0;
    return is64 ? 2 : 1;
}

// ---------------------------------------------------------------------------
// 1) GEMM1: h1 = x @ W1, fp16 out, unscaled.
//    Block tile 128 nodes x 64 outs, thread tile 4 x 8, k-chunks of 16 in smem.
__global__ __launch_bounds__(256) void gemm1_kernel(
    const float* __restrict__ x, const float* __restrict__ W1, int N) {
    __shared__ float Wsh[IN_F][HID_F];   // 16KB
    __shared__ float Xsh[16][128];       // 8KB per k-chunk (transposed)

    int tid = threadIdx.x;
    int tx = tid & 7;          // out group: outs tx*8..tx*8+7
    int ty = tid >> 3;         // node group: nodes ty*4..ty*4+3
    int nb = blockIdx.x * 128;

    for (int i = tid; i < 1024; i += 256) {
        int row = i >> 4, c4 = (i & 15) << 2;
        *reinterpret_cast<float4*>(&Wsh[row][c4]) =
            *reinterpret_cast<const float4*>(&W1[row * HID_F + c4]);
    }

    float acc[4][8];
#pragma unroll
    for (int i = 0; i < 4; i++)
#pragma unroll
        for (int j = 0; j < 8; j++) acc[i][j] = 0.0f;

    for (int kc = 0; kc < 4; kc++) {
        int k0 = kc * 16;
        __syncthreads();
        for (int i = tid; i < 512; i += 256) {
            int node = i >> 2, k4 = (i & 3) << 2;
            float4 v = make_float4(0.f, 0.f, 0.f, 0.f);
            int n = nb + node;
            if (n < N)
                v = *reinterpret_cast<const float4*>(&x[(size_t)n * IN_F + k0 + k4]);
            Xsh[k4 + 0][node] = v.x;
            Xsh[k4 + 1][node] = v.y;
            Xsh[k4 + 2][node] = v.z;
            Xsh[k4 + 3][node] = v.w;
        }
        __syncthreads();
#pragma unroll
        for (int k = 0; k < 16; k++) {
            float4 xv = *reinterpret_cast<const float4*>(&Xsh[k][ty * 4]);
            float4 wa = *reinterpret_cast<const float4*>(&Wsh[k0 + k][tx * 8]);
            float4 wb = *reinterpret_cast<const float4*>(&Wsh[k0 + k][tx * 8 + 4]);
            float xs[4] = {xv.x, xv.y, xv.z, xv.w};
#pragma unroll
            for (int i = 0; i < 4; i++) {
                acc[i][0] += xs[i] * wa.x;
                acc[i][1] += xs[i] * wa.y;
                acc[i][2] += xs[i] * wa.z;
                acc[i][3] += xs[i] * wa.w;
                acc[i][4] += xs[i] * wb.x;
                acc[i][5] += xs[i] * wb.y;
                acc[i][6] += xs[i] * wb.z;
                acc[i][7] += xs[i] * wb.w;
            }
        }
    }

#pragma unroll
    for (int i = 0; i < 4; i++) {
        int n = nb + ty * 4 + i;
        if (n >= N) continue;
        __align__(16) __half2 h[4];
#pragma unroll
        for (int p = 0; p < 4; p++)
            h[p] = __floats2half2_rn(acc[i][p * 2], acc[i][p * 2 + 1]);
        *reinterpret_cast<uint4*>(&g_h1[(size_t)n * HID_F + tx * 8]) =
            *reinterpret_cast<uint4*>(h);
    }
}

// 2) degree histogram on dst
__global__ void build_hist_kernel(const int* __restrict__ ei32, int E) {
    int e = blockIdx.x * blockDim.x + threadIdx.x;
    if (e >= E) return;
    int stride = edge_stride(ei32, E);
    int dst = ei32[((size_t)E + e) * stride];
    atomicAdd(&g_cnt[dst], 1);
}

// 3) per-block exclusive scan of g_cnt -> g_row, block totals -> g_blksum
__global__ void scan1_kernel(int N) {
    __shared__ int sh[SCAN_B];
    int i = blockIdx.x * SCAN_B + threadIdx.x;
    int v = (i < N) ? g_cnt[i] : 0;
    sh[threadIdx.x] = v;
    __syncthreads();
    for (int off = 1; off < SCAN_B; off *= 2) {
        int t = (threadIdx.x >= off) ? sh[threadIdx.x - off] : 0;
        __syncthreads();
        sh[threadIdx.x] += t;
        __syncthreads();
    }
    if (i < N) g_row[i] = sh[threadIdx.x] - v;   // exclusive
    if (threadIdx.x == SCAN_B - 1) g_blksum[blockIdx.x] = sh[SCAN_B - 1];
}

// 4) fixup: each block redundantly scans blk sums (folds scan2);
//    writes final offsets, cursors, dis = rsqrt(deg+1)
__global__ void scan3_kernel(int N, int nblks) {
    __shared__ int incl[MAX_SCAN_BLKS];
    if (threadIdx.x < MAX_SCAN_BLKS)
        incl[threadIdx.x] = (threadIdx.x < nblks) ? g_blksum[threadIdx.x] : 0;
    __syncthreads();
    for (int off = 1; off < MAX_SCAN_BLKS; off *= 2) {
        int t = 0;
        if (threadIdx.x < MAX_SCAN_BLKS && threadIdx.x >= off)
            t = incl[threadIdx.x - off];
        __syncthreads();
        if (threadIdx.x < MAX_SCAN_BLKS) incl[threadIdx.x] += t;
        __syncthreads();
    }
    int i = blockIdx.x * blockDim.x + threadIdx.x;
    if (i >= N) return;
    int b = i >> 10;
    int pre = (b > 0) ? incl[b - 1] : 0;
    int r = g_row[i] + pre;
    g_row[i] = r;
    g_cur[i] = r;
    g_dis[i] = rsqrtf((float)(g_cnt[i] + 1));
}

// 5) bucket fill: csr entry packs (src, dis[src])
__global__ void fill_kernel(const int* __restrict__ ei32, int E) {
    int e = blockIdx.x * blockDim.x + threadIdx.x;
    if (e >= E) return;
    int stride = edge_stride(ei32, E);
    int src = ei32[(size_t)e * stride];
    int dst = ei32[((size_t)E + e) * stride];
    int pos = atomicAdd(&g_cur[dst], 1);
    g_csr[pos] = make_int2(src, __float_as_int(g_dis[src]));
}

// ---------------------------------------------------------------------------
// 6) gather layer 1: agg1[n] = dis[n] * ( dis[n]*h1[n] + sum_s dis[s]*h1[s] )
//    8 threads per node. Subgroup-masked shuffles (trip count uniform in group).
__global__ __launch_bounds__(256) void gather1_kernel(int N) {
    int t = blockIdx.x * blockDim.x + threadIdx.x;
    int n = t >> 3;
    int c = t & 7;
    if (n >= N) return;

    unsigned lane = threadIdx.x & 31;
    unsigned gmask = 0xffu << (lane & ~7u);   // this 8-lane group's mask

    float dn = g_dis[n];
    int beg = g_row[n];
    int cnt = g_cnt[n];

    float acc[8];
    {   // self term: dis[n] * h1[n]
        uint4 raw = *reinterpret_cast<const uint4*>(&g_h1[(size_t)n * HID_F + c * 8]);
        const __half2* hp = reinterpret_cast<const __half2*>(&raw);
#pragma unroll
        for (int p = 0; p < 4; p++) {
            float2 f = __half22float2(hp[p]);
            acc[p * 2 + 0] = dn * f.x;
            acc[p * 2 + 1] = dn * f.y;
        }
    }

    int j = beg, end = beg + cnt;
    for (; j + 2 <= end; j += 2) {
        int2 ld = make_int2(0, 0);
        if (c < 2) ld = g_csr[j + c];
        int   s0 = __shfl_sync(gmask, ld.x, 0, 8);
        float d0 = __int_as_float(__shfl_sync(gmask, ld.y, 0, 8));
        int   s1 = __shfl_sync(gmask, ld.x, 1, 8);
        float d1 = __int_as_float(__shfl_sync(gmask, ld.y, 1, 8));

        uint4 ra = *reinterpret_cast<const uint4*>(&g_h1[(size_t)s0 * HID_F + c * 8]);
        uint4 rb = *reinterpret_cast<const uint4*>(&g_h1[(size_t)s1 * HID_F + c * 8]);
        const __half2* ha = reinterpret_cast<const __half2*>(&ra);
        const __half2* hb = reinterpret_cast<const __half2*>(&rb);
#pragma unroll
        for (int p = 0; p < 4; p++) {
            float2 fa = __half22float2(ha[p]);
            float2 fb = __half22float2(hb[p]);
            acc[p * 2 + 0] += d0 * fa.x + d1 * fb.x;
            acc[p * 2 + 1] += d0 * fa.y + d1 * fb.y;
        }
    }
    if (j < end) {
        int2 ld = make_int2(0, 0);
        if (c == 0) ld = g_csr[j];
        int   s0 = __shfl_sync(gmask, ld.x, 0, 8);
        float d0 = __int_as_float(__shfl_sync(gmask, ld.y, 0, 8));
        uint4 ra = *reinterpret_cast<const uint4*>(&g_h1[(size_t)s0 * HID_F + c * 8]);
        const __half2* ha = reinterpret_cast<const __half2*>(&ra);
#pragma unroll
        for (int p = 0; p < 4; p++) {
            float2 fa = __half22float2(ha[p]);
            acc[p * 2 + 0] += d0 * fa.x;
            acc[p * 2 + 1] += d0 * fa.y;
        }
    }

    float4 o0 = make_float4(acc[0] * dn, acc[1] * dn, acc[2] * dn, acc[3] * dn);
    float4 o1 = make_float4(acc[4] * dn, acc[5] * dn, acc[6] * dn, acc[7] * dn);
    float* dst = &g_agg1[(size_t)n * HID_F + c * 8];
    *reinterpret_cast<float4*>(dst) = o0;
    *reinterpret_cast<float4*>(dst + 4) = o1;
}

// 7) GEMM2: h2 = relu(agg1 + b1) @ W2, unscaled fp32. 2 nodes/thread.
__global__ __launch_bounds__(256) void gemm2_kernel(
    const float* __restrict__ W2, const float* __restrict__ b1, int N) {
    __shared__ float Wsh[HID_F][OUT_F];   // 4KB
    __shared__ float bsh[HID_F];
    for (int i = threadIdx.x; i < HID_F * OUT_F; i += blockDim.x)
        Wsh[i >> 4][i & 15] = W2[i];
    if (threadIdx.x < HID_F) bsh[threadIdx.x] = b1[threadIdx.x];
    __syncthreads();

    int t = blockIdx.x * blockDim.x + threadIdx.x;
    int n0 = t * 2, n1 = t * 2 + 1;
    if (n0 >= N) return;
    bool has1 = (n1 < N);

    float acc0[OUT_F], acc1[OUT_F];
#pragma unroll
    for (int j = 0; j < OUT_F; j++) { acc0[j] = 0.0f; acc1[j] = 0.0f; }

    const float4* a0 = reinterpret_cast<const float4*>(&g_agg1[(size_t)n0 * HID_F]);
    const float4* a1 = reinterpret_cast<const float4*>(&g_agg1[(size_t)n1 * HID_F]);

#pragma unroll 4
    for (int k4 = 0; k4 < HID_F / 4; k4++) {
        float4 v0 = a0[k4];
        float4 v1 = has1 ? a1[k4] : make_float4(0.f, 0.f, 0.f, 0.f);
        float h0s[4] = {v0.x, v0.y, v0.z, v0.w};
        float h1s[4] = {v1.x, v1.y, v1.z, v1.w};
#pragma unroll
        for (int kk = 0; kk < 4; kk++) {
            int k = k4 * 4 + kk;
            float bb = bsh[k];
            float h0 = fmaxf(h0s[kk] + bb, 0.0f);
            float h1 = fmaxf(h1s[kk] + bb, 0.0f);
#pragma unroll
            for (int j4 = 0; j4 < OUT_F / 4; j4++) {
                float4 w = *reinterpret_cast<const float4*>(&Wsh[k][j4 * 4]);
                acc0[j4 * 4 + 0] += h0 * w.x;  acc1[j4 * 4 + 0] += h1 * w.x;
                acc0[j4 * 4 + 1] += h0 * w.y;  acc1[j4 * 4 + 1] += h1 * w.y;
                acc0[j4 * 4 + 2] += h0 * w.z;  acc1[j4 * 4 + 2] += h1 * w.z;
                acc0[j4 * 4 + 3] += h0 * w.w;  acc1[j4 * 4 + 3] += h1 * w.w;
            }
        }
    }

    float4* o0 = reinterpret_cast<float4*>(&g_h2[(size_t)n0 * OUT_F]);
#pragma unroll
    for (int j4 = 0; j4 < OUT_F / 4; j4++)
        o0[j4] = make_float4(acc0[j4 * 4], acc0[j4 * 4 + 1],
                             acc0[j4 * 4 + 2], acc0[j4 * 4 + 3]);
    if (has1) {
        float4* o1 = reinterpret_cast<float4*>(&g_h2[(size_t)n1 * OUT_F]);
#pragma unroll
        for (int j4 = 0; j4 < OUT_F / 4; j4++)
            o1[j4] = make_float4(acc1[j4 * 4], acc1[j4 * 4 + 1],
                                 acc1[j4 * 4 + 2], acc1[j4 * 4 + 3]);
    }
}

// 8) gather layer 2 + log_softmax fused. 4 threads/node, 4 feats each.
//    Subgroup-masked shuffles. Also re-zeroes g_cnt for next replay.
__global__ __launch_bounds__(256) void gather2_lsm_kernel(
    const float* __restrict__ b2, float* __restrict__ out, int N) {
    int t = blockIdx.x * blockDim.x + threadIdx.x;
    int n = t >> 2;
    int c = t & 3;
    if (n >= N) return;

    unsigned lane = threadIdx.x & 31;
    unsigned gmask = 0xfu << (lane & ~3u);   // this 4-lane group's mask

    float dn = g_dis[n];
    int beg = g_row[n];
    int cnt = g_cnt[n];

    float4 self = *reinterpret_cast<const float4*>(&g_h2[(size_t)n * OUT_F + c * 4]);
    float acc[4] = {dn * self.x, dn * self.y, dn * self.z, dn * self.w};

    int j = beg, end = beg + cnt;
    for (; j + 2 <= end; j += 2) {
        int2 ld = make_int2(0, 0);
        if (c < 2) ld = g_csr[j + c];
        int   s0 = __shfl_sync(gmask, ld.x, 0, 4);
        float d0 = __int_as_float(__shfl_sync(gmask, ld.y, 0, 4));
        int   s1 = __shfl_sync(gmask, ld.x, 1, 4);
        float d1 = __int_as_float(__shfl_sync(gmask, ld.y, 1, 4));
        float4 va = *reinterpret_cast<const float4*>(&g_h2[(size_t)s0 * OUT_F + c * 4]);
        float4 vb = *reinterpret_cast<const float4*>(&g_h2[(size_t)s1 * OUT_F + c * 4]);
        acc[0] += d0 * va.x + d1 * vb.x;
        acc[1] += d0 * va.y + d1 * vb.y;
        acc[2] += d0 * va.z + d1 * vb.z;
        acc[3] += d0 * va.w + d1 * vb.w;
    }
    if (j < end) {
        int2 ld = make_int2(0, 0);
        if (c == 0) ld = g_csr[j];
        int   s0 = __shfl_sync(gmask, ld.x, 0, 4);
        float d0 = __int_as_float(__shfl_sync(gmask, ld.y, 0, 4));
        float4 va = *reinterpret_cast<const float4*>(&g_h2[(size_t)s0 * OUT_F + c * 4]);
        acc[0] += d0 * va.x;
        acc[1] += d0 * va.y;
        acc[2] += d0 * va.z;
        acc[3] += d0 * va.w;
    }

    float4 bb = *reinterpret_cast<const float4*>(&b2[c * 4]);
    float v[4] = {acc[0] * dn + bb.x, acc[1] * dn + bb.y,
                  acc[2] * dn + bb.z, acc[3] * dn + bb.w};

    // row reductions across the 4-lane group (group-masked)
    float mx = fmaxf(fmaxf(v[0], v[1]), fmaxf(v[2], v[3]));
    mx = fmaxf(mx, __shfl_xor_sync(gmask, mx, 1, 4));
    mx = fmaxf(mx, __shfl_xor_sync(gmask, mx, 2, 4));
    float s = __expf(v[0] - mx) + __expf(v[1] - mx) +
              __expf(v[2] - mx) + __expf(v[3] - mx);
    s += __shfl_xor_sync(gmask, s, 1, 4);
    s += __shfl_xor_sync(gmask, s, 2, 4);
    float ls = mx + logf(s);

    *reinterpret_cast<float4*>(&out[(size_t)n * OUT_F + c * 4]) =
        make_float4(v[0] - ls, v[1] - ls, v[2] - ls, v[3] - ls);

    if (c == 0) g_cnt[n] = 0;   // ready for next replay
}

// ---------------------------------------------------------------------------
extern "C" void kernel_launch(void* const* d_in, const int* in_sizes, int n_in,
                              void* d_out, int out_size) {
    const float* x    = (const float*)d_in[0];
    const int*   ei32 = (const int*)d_in[1];
    const float* W1   = (const float*)d_in[2];
    const float* b1   = (const float*)d_in[3];
    const float* W2   = (const float*)d_in[4];
    const float* b2   = (const float*)d_in[5];
    float* out = (float*)d_out;

    int N = in_sizes[0] / IN_F;
    int E = in_sizes[1] / 2;

    const int T = 256;
    int gE = (E + T - 1) / T;
    int nScanBlks = (N + SCAN_B - 1) / SCAN_B;

    gemm1_kernel<<<(N + 127) / 128, 256>>>(x, W1, N);                 // 1
    build_hist_kernel<<<gE, T>>>(ei32, E);                            // 2
    scan1_kernel<<<nScanBlks, SCAN_B>>>(N);                           // 3
    scan3_kernel<<<(N + T - 1) / T, T>>>(N, nScanBlks);               // 4
    fill_kernel<<<gE, T>>>(ei32, E);                                  // 5
    gather1_kernel<<<(N * 8 + T - 1) / T, T>>>(N);                    // 6 <- profiled
    gemm2_kernel<<<((N + 1) / 2 + T - 1) / T, T>>>(W2, b1, N);        // 7
    gather2_lsm_kernel<<<(N * 4 + T - 1) / T, T>>>(b2, out, N);       // 8
}

// round 6
// speedup vs baseline: 1.6038x; 1.1146x over previous
#include <cuda_runtime.h>
#include <cuda_fp16.h>
#include <math.h>
#include <stdint.h>

#define N_NODES 100000
#define N_EDGES 1600000
#define IN_F 64
#define HID_F 64
#define OUT_F 16

#define SCAN_B 1024
#define MAX_SCAN_BLKS 128

// ---- scratch (static __device__ globals) ----
__device__ __align__(16) int    g_cnt[N_NODES];     // in-degree (re-zeroed by last kernel)
__device__ __align__(16) int    g_row[N_NODES];     // CSR exclusive offsets (begin)
__device__ __align__(16) int    g_cur[N_NODES];     // fill cursors; after fill == row end
__device__ __align__(16) int    g_blksum[MAX_SCAN_BLKS];
__device__ __align__(16) float  g_dis[N_NODES];     // rsqrt(deg+1)
__device__ __align__(16) int2   g_csr[N_EDGES];     // (src, bits(dis[src]))
__device__ __align__(16) __half g_h1[(size_t)N_NODES * HID_F];  // x@W1 (unscaled, fp16)
__device__ __align__(16) float  g_agg1[(size_t)N_NODES * HID_F];
__device__ __align__(16) float  g_h2[(size_t)N_NODES * OUT_F];  // relu(..)@W2 (unscaled)

// inline dtype detect: int64 node ids < 2^31 have zero odd 32-bit words
__device__ __forceinline__ int edge_stride(const int* __restrict__ ei32, int E) {
    int is64 = 1;
    int n = E < 16 ? E : 16;
#pragma unroll
    for (int i = 0; i < 16; i++)
        if (i < n && ei32[2 * i + 1] != 0) is64 = 0;
    return is64 ? 2 : 1;
}

// ---------------------------------------------------------------------------
// GEMM1: h1 = x @ W1, fp16 out, unscaled.
// Block tile 128 nodes x 64 outs, thread tile 4 x 8, k-chunks of 16 in smem.
__global__ __launch_bounds__(256) void gemm1_kernel(
    const float* __restrict__ x, const float* __restrict__ W1, int N) {
    __shared__ float Wsh[IN_F][HID_F];   // 16KB
    __shared__ float Xsh[16][128];       // 8KB per k-chunk (transposed)

    int tid = threadIdx.x;
    int tx = tid & 7;
    int ty = tid >> 3;
    int nb = blockIdx.x * 128;

    for (int i = tid; i < 1024; i += 256) {
        int row = i >> 4, c4 = (i & 15) << 2;
        *reinterpret_cast<float4*>(&Wsh[row][c4]) =
            *reinterpret_cast<const float4*>(&W1[row * HID_F + c4]);
    }

    float acc[4][8];
#pragma unroll
    for (int i = 0; i < 4; i++)
#pragma unroll
        for (int j = 0; j < 8; j++) acc[i][j] = 0.0f;

    for (int kc = 0; kc < 4; kc++) {
        int k0 = kc * 16;
        __syncthreads();
        for (int i = tid; i < 512; i += 256) {
            int node = i >> 2, k4 = (i & 3) << 2;
            float4 v = make_float4(0.f, 0.f, 0.f, 0.f);
            int n = nb + node;
            if (n < N)
                v = *reinterpret_cast<const float4*>(&x[(size_t)n * IN_F + k0 + k4]);
            Xsh[k4 + 0][node] = v.x;
            Xsh[k4 + 1][node] = v.y;
            Xsh[k4 + 2][node] = v.z;
            Xsh[k4 + 3][node] = v.w;
        }
        __syncthreads();
#pragma unroll
        for (int k = 0; k < 16; k++) {
            float4 xv = *reinterpret_cast<const float4*>(&Xsh[k][ty * 4]);
            float4 wa = *reinterpret_cast<const float4*>(&Wsh[k0 + k][tx * 8]);
            float4 wb = *reinterpret_cast<const float4*>(&Wsh[k0 + k][tx * 8 + 4]);
            float xs[4] = {xv.x, xv.y, xv.z, xv.w};
#pragma unroll
            for (int i = 0; i < 4; i++) {
                acc[i][0] += xs[i] * wa.x;
                acc[i][1] += xs[i] * wa.y;
                acc[i][2] += xs[i] * wa.z;
                acc[i][3] += xs[i] * wa.w;
                acc[i][4] += xs[i] * wb.x;
                acc[i][5] += xs[i] * wb.y;
                acc[i][6] += xs[i] * wb.z;
                acc[i][7] += xs[i] * wb.w;
            }
        }
    }

#pragma unroll
    for (int i = 0; i < 4; i++) {
        int n = nb + ty * 4 + i;
        if (n >= N) continue;
        __align__(16) __half2 h[4];
#pragma unroll
        for (int p = 0; p < 4; p++)
            h[p] = __floats2half2_rn(acc[i][p * 2], acc[i][p * 2 + 1]);
        *reinterpret_cast<uint4*>(&g_h1[(size_t)n * HID_F + tx * 8]) =
            *reinterpret_cast<uint4*>(h);
    }
}

// degree histogram on dst
__global__ void build_hist_kernel(const int* __restrict__ ei32, int E) {
    int e = blockIdx.x * blockDim.x + threadIdx.x;
    if (e >= E) return;
    int stride = edge_stride(ei32, E);
    int dst = ei32[((size_t)E + e) * stride];
    atomicAdd(&g_cnt[dst], 1);
}

// per-block exclusive scan (warp-shuffle, 2 barriers)
__global__ __launch_bounds__(SCAN_B) void scan1_kernel(int N) {
    __shared__ int wsum[32];
    int i = blockIdx.x * SCAN_B + threadIdx.x;
    int v = (i < N) ? g_cnt[i] : 0;
    int lane = threadIdx.x & 31, wid = threadIdx.x >> 5;

    int s = v;
#pragma unroll
    for (int o = 1; o < 32; o *= 2) {
        int t = __shfl_up_sync(0xffffffffu, s, o);
        if (lane >= o) s += t;
    }
    if (lane == 31) wsum[wid] = s;
    __syncthreads();
    if (wid == 0) {
        int w = wsum[lane];
        int ws = w;
#pragma unroll
        for (int o = 1; o < 32; o *= 2) {
            int t = __shfl_up_sync(0xffffffffu, ws, o);
            if (lane >= o) ws += t;
        }
        wsum[lane] = ws - w;                       // exclusive warp offsets
        if (lane == 31) g_blksum[blockIdx.x] = ws; // block total
    }
    __syncthreads();
    if (i < N) g_row[i] = wsum[wid] + s - v;       // exclusive
}

// fixup: warp 0 scans block sums (4/lane), then final offsets + cursors + dis
__global__ void scan3_kernel(int N, int nblks) {
    __shared__ int excl[MAX_SCAN_BLKS];
    int lane = threadIdx.x & 31;
    if (threadIdx.x < 32) {
        int b4 = lane * 4;
        int v0 = (b4 + 0 < nblks) ? g_blksum[b4 + 0] : 0;
        int v1 = (b4 + 1 < nblks) ? g_blksum[b4 + 1] : 0;
        int v2 = (b4 + 2 < nblks) ? g_blksum[b4 + 2] : 0;
        int v3 = (b4 + 3 < nblks) ? g_blksum[b4 + 3] : 0;
        int s4 = v0 + v1 + v2 + v3;
        int ss = s4;
#pragma unroll
        for (int o = 1; o < 32; o *= 2) {
            int t = __shfl_up_sync(0xffffffffu, ss, o);
            if (lane >= o) ss += t;
        }
        int ex = ss - s4;
        excl[b4 + 0] = ex;
        excl[b4 + 1] = ex + v0;
        excl[b4 + 2] = ex + v0 + v1;
        excl[b4 + 3] = ex + v0 + v1 + v2;
    }
    __syncthreads();
    int i = blockIdx.x * blockDim.x + threadIdx.x;
    if (i >= N) return;
    int r = g_row[i] + excl[i >> 10];
    g_row[i] = r;
    g_cur[i] = r;
    g_dis[i] = rsqrtf((float)(g_cnt[i] + 1));
}

// bucket fill: csr entry packs (src, dis[src]); after this g_cur[n] == row end
__global__ void fill_kernel(const int* __restrict__ ei32, int E) {
    int e = blockIdx.x * blockDim.x + threadIdx.x;
    if (e >= E) return;
    int stride = edge_stride(ei32, E);
    int src = ei32[(size_t)e * stride];
    int dst = ei32[((size_t)E + e) * stride];
    int pos = atomicAdd(&g_cur[dst], 1);
    g_csr[pos] = make_int2(src, __float_as_int(g_dis[src]));
}

// ---------------------------------------------------------------------------
// gather layer 1: agg1[n] = dis[n] * ( dis[n]*h1[n] + sum_s dis[s]*h1[s] )
__global__ __launch_bounds__(256) void gather1_kernel(int N) {
    int t = blockIdx.x * blockDim.x + threadIdx.x;
    int n = t >> 3;
    int c = t & 7;
    if (n >= N) return;

    unsigned lane = threadIdx.x & 31;
    unsigned gmask = 0xffu << (lane & ~7u);

    float dn = g_dis[n];
    int beg = g_row[n];
    int end = g_cur[n];   // == row end after fill

    float acc[8];
    {
        uint4 raw = *reinterpret_cast<const uint4*>(&g_h1[(size_t)n * HID_F + c * 8]);
        const __half2* hp = reinterpret_cast<const __half2*>(&raw);
#pragma unroll
        for (int p = 0; p < 4; p++) {
            float2 f = __half22float2(hp[p]);
            acc[p * 2 + 0] = dn * f.x;
            acc[p * 2 + 1] = dn * f.y;
        }
    }

    int j = beg;
    for (; j + 2 <= end; j += 2) {
        int2 ld = make_int2(0, 0);
        if (c < 2) ld = g_csr[j + c];
        int   s0 = __shfl_sync(gmask, ld.x, 0, 8);
        float d0 = __int_as_float(__shfl_sync(gmask, ld.y, 0, 8));
        int   s1 = __shfl_sync(gmask, ld.x, 1, 8);
        float d1 = __int_as_float(__shfl_sync(gmask, ld.y, 1, 8));

        uint4 ra = *reinterpret_cast<const uint4*>(&g_h1[(size_t)s0 * HID_F + c * 8]);
        uint4 rb = *reinterpret_cast<const uint4*>(&g_h1[(size_t)s1 * HID_F + c * 8]);
        const __half2* ha = reinterpret_cast<const __half2*>(&ra);
        const __half2* hb = reinterpret_cast<const __half2*>(&rb);
#pragma unroll
        for (int p = 0; p < 4; p++) {
            float2 fa = __half22float2(ha[p]);
            float2 fb = __half22float2(hb[p]);
            acc[p * 2 + 0] += d0 * fa.x + d1 * fb.x;
            acc[p * 2 + 1] += d0 * fa.y + d1 * fb.y;
        }
    }
    if (j < end) {
        int2 ld = make_int2(0, 0);
        if (c == 0) ld = g_csr[j];
        int   s0 = __shfl_sync(gmask, ld.x, 0, 8);
        float d0 = __int_as_float(__shfl_sync(gmask, ld.y, 0, 8));
        uint4 ra = *reinterpret_cast<const uint4*>(&g_h1[(size_t)s0 * HID_F + c * 8]);
        const __half2* ha = reinterpret_cast<const __half2*>(&ra);
#pragma unroll
        for (int p = 0; p < 4; p++) {
            float2 fa = __half22float2(ha[p]);
            acc[p * 2 + 0] += d0 * fa.x;
            acc[p * 2 + 1] += d0 * fa.y;
        }
    }

    float4 o0 = make_float4(acc[0] * dn, acc[1] * dn, acc[2] * dn, acc[3] * dn);
    float4 o1 = make_float4(acc[4] * dn, acc[5] * dn, acc[6] * dn, acc[7] * dn);
    float* dst = &g_agg1[(size_t)n * HID_F + c * 8];
    *reinterpret_cast<float4*>(dst) = o0;
    *reinterpret_cast<float4*>(dst + 4) = o1;
}

// GEMM2: h2 = relu(agg1 + b1) @ W2, unscaled fp32. 2 nodes/thread.
__global__ __launch_bounds__(256) void gemm2_kernel(
    const float* __restrict__ W2, const float* __restrict__ b1, int N) {
    __shared__ float Wsh[HID_F][OUT_F];
    __shared__ float bsh[HID_F];
    for (int i = threadIdx.x; i < HID_F * OUT_F; i += blockDim.x)
        Wsh[i >> 4][i & 15] = W2[i];
    if (threadIdx.x < HID_F) bsh[threadIdx.x] = b1[threadIdx.x];
    __syncthreads();

    int t = blockIdx.x * blockDim.x + threadIdx.x;
    int n0 = t * 2, n1 = t * 2 + 1;
    if (n0 >= N) return;
    bool has1 = (n1 < N);

    float acc0[OUT_F], acc1[OUT_F];
#pragma unroll
    for (int j = 0; j < OUT_F; j++) { acc0[j] = 0.0f; acc1[j] = 0.0f; }

    const float4* a0 = reinterpret_cast<const float4*>(&g_agg1[(size_t)n0 * HID_F]);
    const float4* a1 = reinterpret_cast<const float4*>(&g_agg1[(size_t)n1 * HID_F]);

#pragma unroll 4
    for (int k4 = 0; k4 < HID_F / 4; k4++) {
        float4 v0 = a0[k4];
        float4 v1 = has1 ? a1[k4] : make_float4(0.f, 0.f, 0.f, 0.f);
        float h0s[4] = {v0.x, v0.y, v0.z, v0.w};
        float h1s[4] = {v1.x, v1.y, v1.z, v1.w};
#pragma unroll
        for (int kk = 0; kk < 4; kk++) {
            int k = k4 * 4 + kk;
            float bb = bsh[k];
            float h0 = fmaxf(h0s[kk] + bb, 0.0f);
            float h1 = fmaxf(h1s[kk] + bb, 0.0f);
#pragma unroll
            for (int j4 = 0; j4 < OUT_F / 4; j4++) {
                float4 w = *reinterpret_cast<const float4*>(&Wsh[k][j4 * 4]);
                acc0[j4 * 4 + 0] += h0 * w.x;  acc1[j4 * 4 + 0] += h1 * w.x;
                acc0[j4 * 4 + 1] += h0 * w.y;  acc1[j4 * 4 + 1] += h1 * w.y;
                acc0[j4 * 4 + 2] += h0 * w.z;  acc1[j4 * 4 + 2] += h1 * w.z;
                acc0[j4 * 4 + 3] += h0 * w.w;  acc1[j4 * 4 + 3] += h1 * w.w;
            }
        }
    }

    float4* o0 = reinterpret_cast<float4*>(&g_h2[(size_t)n0 * OUT_F]);
#pragma unroll
    for (int j4 = 0; j4 < OUT_F / 4; j4++)
        o0[j4] = make_float4(acc0[j4 * 4], acc0[j4 * 4 + 1],
                             acc0[j4 * 4 + 2], acc0[j4 * 4 + 3]);
    if (has1) {
        float4* o1 = reinterpret_cast<float4*>(&g_h2[(size_t)n1 * OUT_F]);
#pragma unroll
        for (int j4 = 0; j4 < OUT_F / 4; j4++)
            o1[j4] = make_float4(acc1[j4 * 4], acc1[j4 * 4 + 1],
                                 acc1[j4 * 4 + 2], acc1[j4 * 4 + 3]);
    }
}

// gather layer 2 + log_softmax fused. 4 threads/node. Re-zeroes g_cnt.
__global__ __launch_bounds__(256) void gather2_lsm_kernel(
    const float* __restrict__ b2, float* __restrict__ out, int N) {
    int t = blockIdx.x * blockDim.x + threadIdx.x;
    int n = t >> 2;
    int c = t & 3;
    if (n >= N) return;

    unsigned lane = threadIdx.x & 31;
    unsigned gmask = 0xfu << (lane & ~3u);

    float dn = g_dis[n];
    int beg = g_row[n];
    int end = g_cur[n];

    float4 self = *reinterpret_cast<const float4*>(&g_h2[(size_t)n * OUT_F + c * 4]);
    float acc[4] = {dn * self.x, dn * self.y, dn * self.z, dn * self.w};

    int j = beg;
    for (; j + 2 <= end; j += 2) {
        int2 ld = make_int2(0, 0);
        if (c < 2) ld = g_csr[j + c];
        int   s0 = __shfl_sync(gmask, ld.x, 0, 4);
        float d0 = __int_as_float(__shfl_sync(gmask, ld.y, 0, 4));
        int   s1 = __shfl_sync(gmask, ld.x, 1, 4);
        float d1 = __int_as_float(__shfl_sync(gmask, ld.y, 1, 4));
        float4 va = *reinterpret_cast<const float4*>(&g_h2[(size_t)s0 * OUT_F + c * 4]);
        float4 vb = *reinterpret_cast<const float4*>(&g_h2[(size_t)s1 * OUT_F + c * 4]);
        acc[0] += d0 * va.x + d1 * vb.x;
        acc[1] += d0 * va.y + d1 * vb.y;
        acc[2] += d0 * va.z + d1 * vb.z;
        acc[3] += d0 * va.w + d1 * vb.w;
    }
    if (j < end) {
        int2 ld = make_int2(0, 0);
        if (c == 0) ld = g_csr[j];
        int   s0 = __shfl_sync(gmask, ld.x, 0, 4);
        float d0 = __int_as_float(__shfl_sync(gmask, ld.y, 0, 4));
        float4 va = *reinterpret_cast<const float4*>(&g_h2[(size_t)s0 * OUT_F + c * 4]);
        acc[0] += d0 * va.x;
        acc[1] += d0 * va.y;
        acc[2] += d0 * va.z;
        acc[3] += d0 * va.w;
    }

    float4 bb = *reinterpret_cast<const float4*>(&b2[c * 4]);
    float v[4] = {acc[0] * dn + bb.x, acc[1] * dn + bb.y,
                  acc[2] * dn + bb.z, acc[3] * dn + bb.w};

    float mx = fmaxf(fmaxf(v[0], v[1]), fmaxf(v[2], v[3]));
    mx = fmaxf(mx, __shfl_xor_sync(gmask, mx, 1, 4));
    mx = fmaxf(mx, __shfl_xor_sync(gmask, mx, 2, 4));
    float s = __expf(v[0] - mx) + __expf(v[1] - mx) +
              __expf(v[2] - mx) + __expf(v[3] - mx);
    s += __shfl_xor_sync(gmask, s, 1, 4);
    s += __shfl_xor_sync(gmask, s, 2, 4);
    float ls = mx + logf(s);

    *reinterpret_cast<float4*>(&out[(size_t)n * OUT_F + c * 4]) =
        make_float4(v[0] - ls, v[1] - ls, v[2] - ls, v[3] - ls);

    if (c == 0) g_cnt[n] = 0;
}

// ---------------------------------------------------------------------------
extern "C" void kernel_launch(void* const* d_in, const int* in_sizes, int n_in,
                              void* d_out, int out_size) {
    const float* x    = (const float*)d_in[0];
    const int*   ei32 = (const int*)d_in[1];
    const float* W1   = (const float*)d_in[2];
    const float* b1   = (const float*)d_in[3];
    const float* W2   = (const float*)d_in[4];
    const float* b2   = (const float*)d_in[5];
    float* out = (float*)d_out;

    int N = in_sizes[0] / IN_F;
    int E = in_sizes[1] / 2;

    const int T = 256;
    int gE = (E + T - 1) / T;
    int gN = (N + T - 1) / T;
    int nScanBlks = (N + SCAN_B - 1) / SCAN_B;

    // one-time resource setup (first call is the uncaptured correctness run)
    static cudaStream_t s_side = 0;
    static cudaEvent_t ev_fork = 0, ev_join = 0;
    static int s_init = 0;
    if (!s_init) {
        s_init = 1;
        if (cudaStreamCreateWithFlags(&s_side, cudaStreamNonBlocking) != cudaSuccess)
            s_side = 0;
        if (s_side) {
            if (cudaEventCreateWithFlags(&ev_fork, cudaEventDisableTiming) != cudaSuccess ||
                cudaEventCreateWithFlags(&ev_join, cudaEventDisableTiming) != cudaSuccess)
                s_side = 0;
        }
    }

    if (s_side) {
        // fork: CSR chain on side stream, gemm1 on main stream, join before gather1
        cudaEventRecord(ev_fork, 0);
        cudaStreamWaitEvent(s_side, ev_fork, 0);

        build_hist_kernel<<<gE, T, 0, s_side>>>(ei32, E);
        scan1_kernel<<<nScanBlks, SCAN_B, 0, s_side>>>(N);
        scan3_kernel<<<gN, T, 0, s_side>>>(N, nScanBlks);
        fill_kernel<<<gE, T, 0, s_side>>>(ei32, E);

        gemm1_kernel<<<(N + 127) / 128, 256>>>(x, W1, N);   // main stream, concurrent

        cudaEventRecord(ev_join, s_side);
        cudaStreamWaitEvent(0, ev_join, 0);
    } else {
        // fallback: sequential on main stream
        gemm1_kernel<<<(N + 127) / 128, 256>>>(x, W1, N);
        build_hist_kernel<<<gE, T>>>(ei32, E);
        scan1_kernel<<<nScanBlks, SCAN_B>>>(N);
        scan3_kernel<<<gN, T>>>(N, nScanBlks);
        fill_kernel<<<gE, T>>>(ei32, E);
    }

    gather1_kernel<<<(N * 8 + T - 1) / T, T>>>(N);
    gemm2_kernel<<<((N + 1) / 2 + T - 1) / T, T>>>(W2, b1, N);
    gather2_lsm_kernel<<<(N * 4 + T - 1) / T, T>>>(b2, out, N);
}